// round 1
// baseline (speedup 1.0000x reference)
#include <cuda_runtime.h>
#include <math.h>
#include <stdint.h>

#define D_MODEL 1024
#define NUM_HEADS 16
#define HEAD_DIM 64
#define BATCH 2
#define SEQ 2048
#define M_TOT (BATCH * SEQ)   // 4096

// ---------------- scratch (static device globals; no allocation) ----------------
__device__ float g_Q[(size_t)M_TOT * D_MODEL];
__device__ float g_K[(size_t)M_TOT * D_MODEL];
__device__ float g_V[(size_t)M_TOT * D_MODEL];
__device__ float g_A[(size_t)M_TOT * D_MODEL];

// ---------------- GEMM: C[M,N] = A[M,K] @ W[N,K]^T, optional fused RoPE ----------------
// BM=BN=64, BK=16, 256 threads (16x16), each thread 4x4 microtile.
template <bool ROPE>
__global__ __launch_bounds__(256)
void gemm_rope_kernel(const float* __restrict__ A,
                      const float* __restrict__ W,
                      float* __restrict__ C,
                      const int* __restrict__ tok)
{
    const int BK = 16;
    __shared__ float As[BK][64];
    __shared__ float Bs[BK][64];

    const int tx = threadIdx.x;      // 0..15  -> n
    const int ty = threadIdx.y;      // 0..15  -> m
    const int tid = ty * 16 + tx;
    const int m0 = blockIdx.y * 64;
    const int n0 = blockIdx.x * 64;

    const int lr = tid >> 2;          // 0..63 row within tile
    const int lk = (tid & 3) * 4;     // 0,4,8,12 k offset

    const float* Aptr = A + (size_t)(m0 + lr) * D_MODEL + lk;
    const float* Wptr = W + (size_t)(n0 + lr) * D_MODEL + lk;

    float acc[4][4];
#pragma unroll
    for (int i = 0; i < 4; i++)
#pragma unroll
        for (int j = 0; j < 4; j++) acc[i][j] = 0.0f;

    for (int k0 = 0; k0 < D_MODEL; k0 += BK) {
        float4 av = *(const float4*)(Aptr + k0);
        float4 bv = *(const float4*)(Wptr + k0);
        __syncthreads();   // previous iteration's consumers done
        As[lk + 0][lr] = av.x; As[lk + 1][lr] = av.y;
        As[lk + 2][lr] = av.z; As[lk + 3][lr] = av.w;
        Bs[lk + 0][lr] = bv.x; Bs[lk + 1][lr] = bv.y;
        Bs[lk + 2][lr] = bv.z; Bs[lk + 3][lr] = bv.w;
        __syncthreads();

#pragma unroll
        for (int kk = 0; kk < BK; kk++) {
            float4 a = *(const float4*)&As[kk][ty * 4];
            float4 b = *(const float4*)&Bs[kk][tx * 4];
            float am[4] = {a.x, a.y, a.z, a.w};
            float bn[4] = {b.x, b.y, b.z, b.w};
#pragma unroll
            for (int i = 0; i < 4; i++)
#pragma unroll
                for (int j = 0; j < 4; j++)
                    acc[i][j] += am[i] * bn[j];
        }
    }

    // epilogue (+ fused RoPE for Q/K). Columns tx*4..tx*4+3 are even-aligned,
    // so each thread owns complete rotation pairs (c,c+1).
#pragma unroll
    for (int i = 0; i < 4; i++) {
        int row = m0 + ty * 4 + i;          // global m
        if (ROPE) {
            int s = row & (SEQ - 1);        // row % SEQ (SEQ power of 2)
            float pos = (float)tok[s];
#pragma unroll
            for (int jp = 0; jp < 4; jp += 2) {
                int col = n0 + tx * 4 + jp;
                int hc = col & (HEAD_DIM - 1);      // even
                // inv_freq = theta^(-hc/64) = exp(-hc * ln(10000)/64)
                float inv = expf(-0.14391156831212787f * (float)hc);
                float ang = pos * inv;
                float sn, cs;
                sincosf(ang, &sn, &cs);
                float xe = acc[i][jp];
                float xo = acc[i][jp + 1];
                acc[i][jp]     = xe * cs - xo * sn;
                acc[i][jp + 1] = xe * sn + xo * cs;
            }
        }
        float4 o = make_float4(acc[i][0], acc[i][1], acc[i][2], acc[i][3]);
        *(float4*)(C + (size_t)row * D_MODEL + n0 + tx * 4) = o;
    }
}

// ---------------- causal flash attention ----------------
// One block = 128 queries of one (b,h); one thread = one query row.
// Per-thread online softmax (no cross-thread reduction).
// smem: Ks[64*64] | Vs[64*64] | Ss[128*65]  (Ss also used to stage Q)
#define ATTN_SMEM ((4096 + 4096 + 128 * 65) * sizeof(float))

__global__ __launch_bounds__(128)
void attn_kernel(const float* __restrict__ Q,
                 const float* __restrict__ K,
                 const float* __restrict__ V,
                 float* __restrict__ O)
{
    extern __shared__ float sm[];
    float* Ks = sm;             // 4096 floats
    float* Vs = sm + 4096;      // 4096 floats
    float* Ss = sm + 8192;      // 128*65 floats

    const int tid = threadIdx.x;
    const int b = blockIdx.z;
    const int h = blockIdx.y;
    const int q0 = blockIdx.x * 128;
    const int qi = q0 + tid;

    const float* Qbase = Q + (size_t)b * SEQ * D_MODEL + h * HEAD_DIM;
    const float* Kbase = K + (size_t)b * SEQ * D_MODEL + h * HEAD_DIM;
    const float* Vbase = V + (size_t)b * SEQ * D_MODEL + h * HEAD_DIM;

    // stage Q tile coalesced through Ss, then read own row into registers
    float4* Qs4 = (float4*)Ss;
    for (int idx = tid; idx < 128 * 16; idx += 128) {
        int r = idx >> 4, c = idx & 15;
        Qs4[idx] = *(const float4*)(Qbase + (size_t)(q0 + r) * D_MODEL + c * 4);
    }
    __syncthreads();
    float4 qv[16];
#pragma unroll
    for (int i = 0; i < 16; i++) qv[i] = Qs4[tid * 16 + i];

    float4 accv[16];
#pragma unroll
    for (int i = 0; i < 16; i++) accv[i] = make_float4(0.f, 0.f, 0.f, 0.f);
    float m_run = -1e30f, l_run = 0.0f;

    const int ktiles = q0 / 64 + 2;     // keys [0, q0+128)

    for (int kt = 0; kt < ktiles; kt++) {
        const int k0 = kt * 64;
        __syncthreads();    // protects qv reads (1st iter) and prior-tile Ks/Vs reads
        for (int idx = tid; idx < 1024; idx += 128) {
            int r = idx >> 4, c = idx & 15;
            ((float4*)Ks)[idx] = *(const float4*)(Kbase + (size_t)(k0 + r) * D_MODEL + c * 4);
            ((float4*)Vs)[idx] = *(const float4*)(Vbase + (size_t)(k0 + r) * D_MODEL + c * 4);
        }
        __syncthreads();

        float* srow = Ss + tid * 65;
        const float4* K4 = (const float4*)Ks;
        float mt = -1e30f;
        for (int j = 0; j < 64; j++) {
            float sx = 0.f, sy = 0.f, sz = 0.f, sw = 0.f;
#pragma unroll
            for (int d = 0; d < 16; d++) {
                float4 kv = K4[j * 16 + d];
                sx += qv[d].x * kv.x;
                sy += qv[d].y * kv.y;
                sz += qv[d].z * kv.z;
                sw += qv[d].w * kv.w;
            }
            float s = (sx + sy + sz + sw) * 0.125f;   // 1/sqrt(64)
            if (k0 + j > qi) s = -1e30f;
            mt = fmaxf(mt, s);
            srow[j] = s;
        }

        float m_new = fmaxf(m_run, mt);
        float scale = __expf(m_run - m_new);
        float lsum = 0.f;
        for (int j = 0; j < 64; j++) {
            float p = __expf(srow[j] - m_new);
            lsum += p;
            srow[j] = p;
        }
        l_run = l_run * scale + lsum;
        m_run = m_new;

#pragma unroll
        for (int i = 0; i < 16; i++) {
            accv[i].x *= scale; accv[i].y *= scale;
            accv[i].z *= scale; accv[i].w *= scale;
        }
        const float4* V4 = (const float4*)Vs;
        for (int j = 0; j < 64; j++) {
            float p = srow[j];
#pragma unroll
            for (int d = 0; d < 16; d++) {
                float4 v = V4[j * 16 + d];
                accv[d].x += p * v.x;
                accv[d].y += p * v.y;
                accv[d].z += p * v.z;
                accv[d].w += p * v.w;
            }
        }
    }

    float inv = 1.0f / l_run;
    float* Optr = O + (size_t)(b * SEQ + qi) * D_MODEL + h * HEAD_DIM;
#pragma unroll
    for (int d = 0; d < 16; d++) {
        float4 o = make_float4(accv[d].x * inv, accv[d].y * inv,
                               accv[d].z * inv, accv[d].w * inv);
        *(float4*)(Optr + d * 4) = o;
    }
}

// ---------------- launch ----------------
extern "C" void kernel_launch(void* const* d_in, const int* in_sizes, int n_in,
                              void* d_out, int out_size)
{
    const float* x   = (const float*)d_in[0];
    const int*   tok = (const int*)d_in[1];
    const float* wq  = (const float*)d_in[2];
    const float* wk  = (const float*)d_in[3];
    const float* wv  = (const float*)d_in[4];
    const float* wo  = (const float*)d_in[5];
    float* out = (float*)d_out;

    float *Qb, *Kb, *Vb, *Ab;
    cudaGetSymbolAddress((void**)&Qb, g_Q);
    cudaGetSymbolAddress((void**)&Kb, g_K);
    cudaGetSymbolAddress((void**)&Vb, g_V);
    cudaGetSymbolAddress((void**)&Ab, g_A);

    dim3 gblk(16, 16);
    dim3 ggrid(D_MODEL / 64, M_TOT / 64);   // (16, 64)

    gemm_rope_kernel<true ><<<ggrid, gblk>>>(x, wq, Qb, tok);
    gemm_rope_kernel<true ><<<ggrid, gblk>>>(x, wk, Kb, tok);
    gemm_rope_kernel<false><<<ggrid, gblk>>>(x, wv, Vb, nullptr);

    cudaFuncSetAttribute(attn_kernel,
                         cudaFuncAttributeMaxDynamicSharedMemorySize,
                         (int)ATTN_SMEM);
    attn_kernel<<<dim3(SEQ / 128, NUM_HEADS, BATCH), 128, ATTN_SMEM>>>(Qb, Kb, Vb, Ab);

    gemm_rope_kernel<false><<<ggrid, gblk>>>(Ab, wo, out, nullptr);
}

// round 2
// speedup vs baseline: 1.4976x; 1.4976x over previous
#include <cuda_runtime.h>
#include <math.h>
#include <stdint.h>

#define D_MODEL 1024
#define NUM_HEADS 16
#define HEAD_DIM 64
#define BATCH 2
#define SEQ 2048
#define M_TOT (BATCH * SEQ)   // 4096

// ---------------- scratch (static device globals; no allocation) ----------------
__device__ float g_Q[(size_t)M_TOT * D_MODEL];
__device__ float g_K[(size_t)M_TOT * D_MODEL];
__device__ float g_V[(size_t)M_TOT * D_MODEL];
__device__ float g_A[(size_t)M_TOT * D_MODEL];

// ---------------- tf32 helpers ----------------
__device__ __forceinline__ uint32_t f2tf(float x) {
    uint32_t r;
    asm("cvt.rna.tf32.f32 %0, %1;" : "=r"(r) : "f"(x));
    return r;
}
__device__ __forceinline__ void split_tf(float x, uint32_t& hi, uint32_t& lo) {
    uint32_t h = f2tf(x);
    hi = h;
    lo = f2tf(x - __uint_as_float(h));
}
// D += A * B  (m16n8k8, tf32 inputs, f32 accum)
__device__ __forceinline__ void mma8(float* c, const uint32_t* a, const uint32_t* b) {
    asm volatile(
        "mma.sync.aligned.m16n8k8.row.col.f32.tf32.tf32.f32 "
        "{%0,%1,%2,%3}, {%4,%5,%6,%7}, {%8,%9}, {%0,%1,%2,%3};"
        : "+f"(c[0]), "+f"(c[1]), "+f"(c[2]), "+f"(c[3])
        : "r"(a[0]), "r"(a[1]), "r"(a[2]), "r"(a[3]), "r"(b[0]), "r"(b[1]));
}

// ---------------- projection GEMM: C[M,N] = A[M,K] @ W[N,K]^T  (3xTF32, fused RoPE) ----------
// BM=BN=128, BK=16, 256 threads = 8 warps, warp tile 64x32.
#define PJ_STR 20   // smem k-stride (pad for conflict-free fragment loads, float4-aligned)

template <bool ROPE>
__global__ __launch_bounds__(256)
void proj_kernel(const float* __restrict__ A,
                 const float* __restrict__ W,
                 float* __restrict__ C,
                 const int* __restrict__ tok)
{
    __shared__ float As[128 * PJ_STR];
    __shared__ float Bs[128 * PJ_STR];

    const int tid  = threadIdx.x;
    const int wid  = tid >> 5;
    const int lane = tid & 31;
    const int g = lane >> 2;     // 0..7
    const int t = lane & 3;      // 0..3
    const int wm = (wid & 1) * 64;
    const int wn = (wid >> 1) * 32;
    const int m0 = blockIdx.y * 128;
    const int n0 = blockIdx.x * 128;

    const int lrow = tid >> 1;
    const int lk   = (tid & 1) * 8;
    const float* Ag = A + (size_t)(m0 + lrow) * D_MODEL + lk;
    const float* Wg = W + (size_t)(n0 + lrow) * D_MODEL + lk;

    float acc[4][4][4];
#pragma unroll
    for (int i = 0; i < 4; i++)
#pragma unroll
        for (int j = 0; j < 4; j++)
#pragma unroll
            for (int r = 0; r < 4; r++) acc[i][j][r] = 0.0f;

    for (int k0 = 0; k0 < D_MODEL; k0 += 16) {
        float4 av0 = *(const float4*)(Ag + k0);
        float4 av1 = *(const float4*)(Ag + k0 + 4);
        float4 bv0 = *(const float4*)(Wg + k0);
        float4 bv1 = *(const float4*)(Wg + k0 + 4);
        __syncthreads();
        *(float4*)&As[lrow * PJ_STR + lk]     = av0;
        *(float4*)&As[lrow * PJ_STR + lk + 4] = av1;
        *(float4*)&Bs[lrow * PJ_STR + lk]     = bv0;
        *(float4*)&Bs[lrow * PJ_STR + lk + 4] = bv1;
        __syncthreads();

#pragma unroll
        for (int ks = 0; ks < 16; ks += 8) {
            uint32_t ah[4][4], al[4][4], bh[4][2], bl[4][2];
#pragma unroll
            for (int mi = 0; mi < 4; mi++) {
                int row = wm + mi * 16;
                split_tf(As[(row + g)     * PJ_STR + ks + t],     ah[mi][0], al[mi][0]);
                split_tf(As[(row + g + 8) * PJ_STR + ks + t],     ah[mi][1], al[mi][1]);
                split_tf(As[(row + g)     * PJ_STR + ks + t + 4], ah[mi][2], al[mi][2]);
                split_tf(As[(row + g + 8) * PJ_STR + ks + t + 4], ah[mi][3], al[mi][3]);
            }
#pragma unroll
            for (int nj = 0; nj < 4; nj++) {
                int col = wn + nj * 8;
                split_tf(Bs[(col + g) * PJ_STR + ks + t],     bh[nj][0], bl[nj][0]);
                split_tf(Bs[(col + g) * PJ_STR + ks + t + 4], bh[nj][1], bl[nj][1]);
            }
#pragma unroll
            for (int mi = 0; mi < 4; mi++)
#pragma unroll
                for (int nj = 0; nj < 4; nj++) {
                    mma8(acc[mi][nj], ah[mi], bl[nj]);
                    mma8(acc[mi][nj], al[mi], bh[nj]);
                    mma8(acc[mi][nj], ah[mi], bh[nj]);
                }
        }
    }

    // epilogue (+ fused RoPE)
#pragma unroll
    for (int mi = 0; mi < 4; mi++) {
#pragma unroll
        for (int nj = 0; nj < 4; nj++) {
            int row1 = m0 + wm + mi * 16 + g;
            int row2 = row1 + 8;
            int col  = n0 + wn + nj * 8 + 2 * t;   // even
            float c0 = acc[mi][nj][0], c1 = acc[mi][nj][1];
            float c2 = acc[mi][nj][2], c3 = acc[mi][nj][3];
            if (ROPE) {
                int hc = col & (HEAD_DIM - 1);
                float inv = expf(-0.14391156831212787f * (float)hc);
                float p1 = (float)tok[row1 & (SEQ - 1)];
                float p2 = (float)tok[row2 & (SEQ - 1)];
                float s1, co1, s2, co2;
                sincosf(p1 * inv, &s1, &co1);
                sincosf(p2 * inv, &s2, &co2);
                float e0 = c0, o0 = c1;
                c0 = e0 * co1 - o0 * s1;
                c1 = e0 * s1 + o0 * co1;
                float e2 = c2, o2 = c3;
                c2 = e2 * co2 - o2 * s2;
                c3 = e2 * s2 + o2 * co2;
            }
            *(float2*)(C + (size_t)row1 * D_MODEL + col) = make_float2(c0, c1);
            *(float2*)(C + (size_t)row2 * D_MODEL + col) = make_float2(c2, c3);
        }
    }
}

// ---------------- causal flash attention (tensor-core, 3xTF32) ----------------
// Block = 64 queries of one (b,h), 128 threads = 4 warps (warp w -> rows w*16..w*16+15).
#define AT_STR 68   // smem row stride (floats): conflict-free fragment loads
#define ATTN_SMEM_F (3 * 64 * AT_STR + 3 * 64)
#define ATTN_SMEM_B (ATTN_SMEM_F * sizeof(float))

__global__ __launch_bounds__(128)
void attn_kernel(const float* __restrict__ Q,
                 const float* __restrict__ K,
                 const float* __restrict__ V,
                 float* __restrict__ O)
{
    extern __shared__ float sm[];
    float* Ks    = sm;                      // 64*68
    float* Vs    = sm + 64 * AT_STR;        // 64*68
    float* Ss    = sm + 2 * 64 * AT_STR;    // 64*68
    float* m_run = sm + 3 * 64 * AT_STR;    // 64
    float* l_run = m_run + 64;              // 64
    float* scl   = l_run + 64;              // 64

    const int tid  = threadIdx.x;
    const int w    = tid >> 5;
    const int lane = tid & 31;
    const int g = lane >> 2;
    const int t = lane & 3;
    const int qt = blockIdx.x;
    const int h  = blockIdx.y;
    const int b  = blockIdx.z;
    const int q0 = qt * 64;
    const int qr = w * 16;

    if (tid < 64) { m_run[tid] = -1e30f; l_run[tid] = 0.0f; }

    const float* Qb = Q + (size_t)b * SEQ * D_MODEL + h * HEAD_DIM;
    const float* Kb = K + (size_t)b * SEQ * D_MODEL + h * HEAD_DIM;
    const float* Vb = V + (size_t)b * SEQ * D_MODEL + h * HEAD_DIM;

    // stage Q (pre-scaled by 1/sqrt(64)) into Ks, then lift fragments to regs
    for (int i = tid; i < 64 * 16; i += 128) {
        int r = i >> 4, c4 = (i & 15) * 4;
        float4 v = *(const float4*)(Qb + (size_t)(q0 + r) * D_MODEL + c4);
        v.x *= 0.125f; v.y *= 0.125f; v.z *= 0.125f; v.w *= 0.125f;
        *(float4*)&Ks[r * AT_STR + c4] = v;
    }
    __syncthreads();

    uint32_t qh[8][4], ql[8][4];
#pragma unroll
    for (int ks = 0; ks < 8; ks++) {
        int kc = ks * 8;
        split_tf(Ks[(qr + g)     * AT_STR + kc + t],     qh[ks][0], ql[ks][0]);
        split_tf(Ks[(qr + g + 8) * AT_STR + kc + t],     qh[ks][1], ql[ks][1]);
        split_tf(Ks[(qr + g)     * AT_STR + kc + t + 4], qh[ks][2], ql[ks][2]);
        split_tf(Ks[(qr + g + 8) * AT_STR + kc + t + 4], qh[ks][3], ql[ks][3]);
    }
    __syncthreads();

    float oacc[8][4];
#pragma unroll
    for (int j = 0; j < 8; j++)
#pragma unroll
        for (int r = 0; r < 4; r++) oacc[j][r] = 0.0f;

    const int ntiles = qt + 1;
    for (int kt = 0; kt < ntiles; kt++) {
        const int k0 = kt * 64;
        for (int i = tid; i < 64 * 16; i += 128) {
            int r = i >> 4, c4 = (i & 15) * 4;
            *(float4*)&Ks[r * AT_STR + c4] =
                *(const float4*)(Kb + (size_t)(k0 + r) * D_MODEL + c4);
            *(float4*)&Vs[r * AT_STR + c4] =
                *(const float4*)(Vb + (size_t)(k0 + r) * D_MODEL + c4);
        }
        __syncthreads();

        // ---- S = Q @ K^T (warp rows qr..qr+15, all 64 keys) ----
        float sacc[8][4];
#pragma unroll
        for (int j = 0; j < 8; j++)
#pragma unroll
            for (int r = 0; r < 4; r++) sacc[j][r] = 0.0f;

#pragma unroll
        for (int j = 0; j < 8; j++) {
            int key = j * 8 + g;
#pragma unroll
            for (int ks = 0; ks < 8; ks++) {
                int d = ks * 8 + t;
                uint32_t bh[2], bl[2];
                split_tf(Ks[key * AT_STR + d],     bh[0], bl[0]);
                split_tf(Ks[key * AT_STR + d + 4], bh[1], bl[1]);
                mma8(sacc[j], qh[ks], bl);
                mma8(sacc[j], ql[ks], bh);
                mma8(sacc[j], qh[ks], bh);
            }
        }
        // store S fragments
#pragma unroll
        for (int j = 0; j < 8; j++) {
            int c = j * 8 + 2 * t;
            *(float2*)&Ss[(qr + g)     * AT_STR + c] = make_float2(sacc[j][0], sacc[j][1]);
            *(float2*)&Ss[(qr + g + 8) * AT_STR + c] = make_float2(sacc[j][2], sacc[j][3]);
        }
        __syncthreads();

        // ---- online softmax: 2 threads per row ----
        {
            int row  = tid >> 1;
            int half = tid & 1;
            int qi   = q0 + row;
            int base = half * 32;
            float lm = -1e30f;
            for (int c = 0; c < 32; c++) {
                int col = base + c;
                float s = Ss[row * AT_STR + col];
                if (k0 + col <= qi) lm = fmaxf(lm, s);
            }
            float tm = fmaxf(lm, __shfl_xor_sync(0xffffffffu, lm, 1));
            float mo = m_run[row];
            float mn = fmaxf(mo, tm);
            float ls = 0.0f;
            for (int c = 0; c < 32; c++) {
                int col = base + c;
                float s = Ss[row * AT_STR + col];
                float p = (k0 + col <= qi) ? __expf(s - mn) : 0.0f;
                Ss[row * AT_STR + col] = p;
                ls += p;
            }
            ls += __shfl_xor_sync(0xffffffffu, ls, 1);
            if (half == 0) {
                float sc = __expf(mo - mn);
                scl[row]   = sc;
                l_run[row] = l_run[row] * sc + ls;
                m_run[row] = mn;
            }
        }
        __syncthreads();

        // ---- rescale O, then O += P @ V ----
        {
            float sa = scl[qr + g];
            float sb = scl[qr + g + 8];
#pragma unroll
            for (int j = 0; j < 8; j++) {
                oacc[j][0] *= sa; oacc[j][1] *= sa;
                oacc[j][2] *= sb; oacc[j][3] *= sb;
            }
        }
#pragma unroll
        for (int ks = 0; ks < 8; ks++) {
            int kk = ks * 8;
            uint32_t ah[4], al[4];
            split_tf(Ss[(qr + g)     * AT_STR + kk + t],     ah[0], al[0]);
            split_tf(Ss[(qr + g + 8) * AT_STR + kk + t],     ah[1], al[1]);
            split_tf(Ss[(qr + g)     * AT_STR + kk + t + 4], ah[2], al[2]);
            split_tf(Ss[(qr + g + 8) * AT_STR + kk + t + 4], ah[3], al[3]);
#pragma unroll
            for (int j = 0; j < 8; j++) {
                uint32_t bh[2], bl[2];
                split_tf(Vs[(kk + t)     * AT_STR + j * 8 + g], bh[0], bl[0]);
                split_tf(Vs[(kk + t + 4) * AT_STR + j * 8 + g], bh[1], bl[1]);
                mma8(oacc[j], ah, bl);
                mma8(oacc[j], al, bh);
                mma8(oacc[j], ah, bh);
            }
        }
        __syncthreads();   // protect Ks/Vs/Ss/scl for next tile
    }

    // ---- epilogue: normalize + store ----
    float ia = 1.0f / l_run[qr + g];
    float ib = 1.0f / l_run[qr + g + 8];
    float* Ob = O + ((size_t)b * SEQ + q0) * D_MODEL + h * HEAD_DIM;
#pragma unroll
    for (int j = 0; j < 8; j++) {
        int c = j * 8 + 2 * t;
        *(float2*)&Ob[(size_t)(qr + g) * D_MODEL + c] =
            make_float2(oacc[j][0] * ia, oacc[j][1] * ia);
        *(float2*)&Ob[(size_t)(qr + g + 8) * D_MODEL + c] =
            make_float2(oacc[j][2] * ib, oacc[j][3] * ib);
    }
}

// ---------------- launch ----------------
extern "C" void kernel_launch(void* const* d_in, const int* in_sizes, int n_in,
                              void* d_out, int out_size)
{
    const float* x   = (const float*)d_in[0];
    const int*   tok = (const int*)d_in[1];
    const float* wq  = (const float*)d_in[2];
    const float* wk  = (const float*)d_in[3];
    const float* wv  = (const float*)d_in[4];
    const float* wo  = (const float*)d_in[5];
    float* out = (float*)d_out;

    float *Qb, *Kb, *Vb, *Ab;
    cudaGetSymbolAddress((void**)&Qb, g_Q);
    cudaGetSymbolAddress((void**)&Kb, g_K);
    cudaGetSymbolAddress((void**)&Vb, g_V);
    cudaGetSymbolAddress((void**)&Ab, g_A);

    dim3 pgrid(D_MODEL / 128, M_TOT / 128);   // (8, 32)

    proj_kernel<true ><<<pgrid, 256>>>(x, wq, Qb, tok);
    proj_kernel<true ><<<pgrid, 256>>>(x, wk, Kb, tok);
    proj_kernel<false><<<pgrid, 256>>>(x, wv, Vb, nullptr);

    cudaFuncSetAttribute(attn_kernel,
                         cudaFuncAttributeMaxDynamicSharedMemorySize,
                         (int)ATTN_SMEM_B);
    attn_kernel<<<dim3(SEQ / 64, NUM_HEADS, BATCH), 128, ATTN_SMEM_B>>>(Qb, Kb, Vb, Ab);

    proj_kernel<false><<<pgrid, 256>>>(Ab, wo, out, nullptr);
}